// round 15
// baseline (speedup 1.0000x reference)
#include <cuda_runtime.h>
#include <cuda_fp16.h>
#include <cstdint>

// Problem constants
#define B_TOT 12288   // features(4096) + queue(8192)
#define N_OUT 4096
#define KCLS  1000
#define KPAD  1024
#define DDIM  256
#define INV_EPS 20.0f

// ---------------------------------------------------------------------------
// Device scratch (allocation-free)
// ---------------------------------------------------------------------------
__device__ __half  g_Eh[B_TOT * KPAD];  // exp(logits/eps) in fp16, [b,1024] (25 MB)
__device__ __half  g_Ah[B_TOT * DDIM];  // normalized features, fp16
__device__ __half  g_Bh[KPAD * DDIM];   // normalized head^T, fp16 (pad rows stay 0)
__device__ float   g_u[KPAD];
__device__ float   g_r[KPAD];
__device__ double  g_S;
__device__ float   g_SfB;               // (float)(S / B_TOT), set by finalize_r
__device__ int     g_cnt;               // last-block ticket (self-resetting)

__device__ __forceinline__ float warp_sum(float v) {
    #pragma unroll
    for (int o = 16; o > 0; o >>= 1) v += __shfl_down_sync(0xFFFFFFFFu, v, o);
    return v;
}

__device__ __forceinline__ uint32_t smem_u32(const void* p) {
    uint32_t a;
    asm("{ .reg .u64 t; cvta.to.shared.u64 t, %1; cvt.u32.u64 %0, t; }" : "=r"(a) : "l"(p));
    return a;
}

#define SW64(o) ((o) ^ (((o) >> 3) & 0x30))

__device__ __forceinline__ void ldsm_x4(uint32_t& r0, uint32_t& r1, uint32_t& r2, uint32_t& r3,
                                        uint32_t addr) {
    asm volatile("ldmatrix.sync.aligned.m8n8.x4.shared.b16 {%0,%1,%2,%3}, [%4];"
                 : "=r"(r0), "=r"(r1), "=r"(r2), "=r"(r3) : "r"(addr));
}

__device__ __forceinline__ void mma_f16(float* d, const uint32_t* a, const uint32_t* b) {
    asm volatile(
        "mma.sync.aligned.m16n8k16.row.col.f32.f16.f16.f32 "
        "{%0,%1,%2,%3}, {%4,%5,%6,%7}, {%8,%9}, {%0,%1,%2,%3};"
        : "+f"(d[0]), "+f"(d[1]), "+f"(d[2]), "+f"(d[3])
        : "r"(a[0]), "r"(a[1]), "r"(a[2]), "r"(a[3]), "r"(b[0]), "r"(b[1]));
}

__device__ __forceinline__ void cp_async16(uint32_t dst, const void* src) {
    asm volatile("cp.async.cg.shared.global [%0], [%1], 16;" :: "r"(dst), "l"(src));
}
__device__ __forceinline__ void cp_commit() {
    asm volatile("cp.async.commit_group;" ::: "memory");
}
template <int N> __device__ __forceinline__ void cp_wait() {
    asm volatile("cp.async.wait_group %0;" :: "n"(N) : "memory");
}

// Shared helper: compute r from (S, u), zero u, reset ticket, publish S/B as
// float. Call from the LAST block of a kernel (all threads of that block).
__device__ __forceinline__ void finalize_r(int tid) {
    double S = g_S;
    for (int k = tid; k < KPAD; k += 256) {
        float u;
        asm volatile("ld.global.cg.f32 %0, [%1];" : "=f"(u) : "l"(&g_u[k]));
        g_r[k] = (k < KCLS) ? (float)(S / ((double)KCLS * (double)u)) : 0.f;
        g_u[k] = 0.f;
    }
    if (tid == 0) {
        g_SfB = (float)(S / (double)B_TOT);
        g_cnt = 0;
    }
}

// ---------------------------------------------------------------------------
// 1. Merged prep: blocks [0,1536) normalize feature rows -> fp16 (warp/row);
//    blocks [1536,1792) normalize head dim d -> transposed fp16.
// ---------------------------------------------------------------------------
#define FEAT_BLOCKS (B_TOT / 8)          // 1536
#define PREP_GRID (FEAT_BLOCKS + DDIM)   // 1792

__global__ __launch_bounds__(256) void k_prep(const float* __restrict__ features,
                                              const float* __restrict__ queue,
                                              const float* __restrict__ head) {
    if (blockIdx.x == 0 && threadIdx.x == 0) g_S = 0.0;

    if (blockIdx.x < FEAT_BLOCKS) {
        int gwarp = (blockIdx.x * 256 + threadIdx.x) >> 5;
        int lane  = threadIdx.x & 31;
        const float* row = (gwarp < N_OUT) ? (features + (size_t)gwarp * DDIM)
                                           : (queue + (size_t)(gwarp - N_OUT) * DDIM);
        float x[8];
        const float4* r4 = reinterpret_cast<const float4*>(row + lane * 8);
        float4 v0 = r4[0], v1 = r4[1];
        x[0]=v0.x; x[1]=v0.y; x[2]=v0.z; x[3]=v0.w;
        x[4]=v1.x; x[5]=v1.y; x[6]=v1.z; x[7]=v1.w;
        float ss = 0.f;
        #pragma unroll
        for (int i = 0; i < 8; i++) ss += x[i] * x[i];
        ss = warp_sum(ss);
        ss = __shfl_sync(0xFFFFFFFFu, ss, 0);
        float inv = 1.0f / fmaxf(sqrtf(ss), 1e-12f);
        __half h[8];
        #pragma unroll
        for (int i = 0; i < 8; i++) h[i] = __float2half(x[i] * inv);
        *reinterpret_cast<uint4*>(&g_Ah[(size_t)gwarp * DDIM + lane * 8]) =
            *reinterpret_cast<uint4*>(h);
    } else {
        int d = blockIdx.x - FEAT_BLOCKS;
        const float* row = head + (size_t)d * KCLS;
        float ss = 0.f;
        for (int k = threadIdx.x; k < KCLS; k += 256) {
            float v = row[k];
            ss += v * v;
        }
        __shared__ float sred[8];
        ss = warp_sum(ss);
        if ((threadIdx.x & 31) == 0) sred[threadIdx.x >> 5] = ss;
        __syncthreads();
        if (threadIdx.x < 8) {
            float s = sred[threadIdx.x];
            #pragma unroll
            for (int o = 4; o > 0; o >>= 1) s += __shfl_down_sync(0xFFu, s, o);
            if (threadIdx.x == 0) sred[0] = 1.0f / fmaxf(sqrtf(s), 1e-12f);
        }
        __syncthreads();
        float inv = sred[0];
        for (int k = threadIdx.x; k < KCLS; k += 256)
            g_Bh[(size_t)k * DDIM + d] = __float2half(row[k] * inv);
    }
}

// ---------------------------------------------------------------------------
// 2. HMMA GEMM + exp, single fp16 pass, 3-stage cp.async pipeline.
//    E stored as fp16 (half the write traffic). Last block computes r1.
// ---------------------------------------------------------------------------
#define CH 32
#define NCH 8
#define TILE_BYTES 8192                   // 128 rows x 64B
#define STAGE_BYTES (2 * TILE_BYTES)      // A, B
#define NSTAGE 3
#define SMEM_GEMM_TOTAL (NSTAGE * STAGE_BYTES + 512)
#define GEMM_GRID (8 * 96)

__device__ __forceinline__ void load_stage(uint32_t sbase, int buf, int b0, int n0,
                                           int c, int tid) {
    uint32_t dstb = sbase + (uint32_t)buf * STAGE_BYTES;
    #pragma unroll
    for (int j = 0; j < 2; j++) {
        int slot = tid + j * 256;          // 0..511
        int row  = slot >> 2;
        int c16  = slot & 3;
        uint32_t sw = SW64((uint32_t)(row * 64 + c16 * 16));
        size_t gA = (size_t)(b0 + row) * DDIM + c * CH + c16 * 8;
        size_t gB = (size_t)(n0 + row) * DDIM + c * CH + c16 * 8;
        cp_async16(dstb + 0 * TILE_BYTES + sw, &g_Ah[gA]);
        cp_async16(dstb + 1 * TILE_BYTES + sw, &g_Bh[gB]);
    }
}

__global__ __launch_bounds__(256, 2) void k_gemm_mma() {
    extern __shared__ char smem[];
    float* scol = reinterpret_cast<float*>(smem + NSTAGE * STAGE_BYTES);
    __shared__ int sLast;
    uint32_t sbase = smem_u32(smem);

    int tid = threadIdx.x, wid = tid >> 5, lane = tid & 31;
    int n0 = blockIdx.x * 128;
    int b0 = blockIdx.y * 128;
    int wm = (wid & 1) * 64;
    int wn = (wid >> 1) * 32;

    float acc[4][4][4];
    #pragma unroll
    for (int i = 0; i < 4; i++)
        #pragma unroll
        for (int j = 0; j < 4; j++)
            #pragma unroll
            for (int q = 0; q < 4; q++) acc[i][j][q] = 0.f;

    int a_row  = (lane & 7) + ((lane >> 3) & 1) * 8;
    int a_colb = (lane >> 4) * 16;
    int b_row  = (lane & 7) + ((lane >> 4) & 1) * 8;
    int b_colb = ((lane >> 3) & 1) * 16;

    #pragma unroll
    for (int s = 0; s < NSTAGE; s++) { load_stage(sbase, s, b0, n0, s, tid); cp_commit(); }

    for (int c = 0; c < NCH; c++) {
        cp_wait<NSTAGE - 1>();
        __syncthreads();
        uint32_t tb = sbase + (uint32_t)(c % NSTAGE) * STAGE_BYTES;

        #pragma unroll
        for (int ks = 0; ks < 2; ks++) {
            uint32_t a[4][4], bh[4][2];
            #pragma unroll
            for (int np = 0; np < 2; np++) {
                uint32_t sw = SW64((uint32_t)((wn + np * 16 + b_row) * 64 + ks * 32 + b_colb));
                ldsm_x4(bh[np*2][0], bh[np*2][1], bh[np*2+1][0], bh[np*2+1][1],
                        tb + 1 * TILE_BYTES + sw);
            }
            #pragma unroll
            for (int mt = 0; mt < 4; mt++) {
                uint32_t sw = SW64((uint32_t)((wm + mt * 16 + a_row) * 64 + ks * 32 + a_colb));
                ldsm_x4(a[mt][0], a[mt][1], a[mt][2], a[mt][3], tb + 0 * TILE_BYTES + sw);
            }
            #pragma unroll
            for (int mt = 0; mt < 4; mt++)
                #pragma unroll
                for (int nt = 0; nt < 4; nt++)
                    mma_f16(acc[mt][nt], a[mt], bh[nt]);
        }
        __syncthreads();
        if (c + NSTAGE < NCH) load_stage(sbase, c % NSTAGE, b0, n0, c + NSTAGE, tid);
        cp_commit();
    }

    // ---- Epilogue: exp, fp16 stores, column sums ----
    if (tid < 128) scol[tid] = 0.f;
    __syncthreads();

    int g = lane >> 2;
    int t2 = (lane & 3) * 2;
    float csum[4][2];
    #pragma unroll
    for (int nt = 0; nt < 4; nt++) { csum[nt][0] = 0.f; csum[nt][1] = 0.f; }

    #pragma unroll
    for (int mt = 0; mt < 4; mt++) {
        int r0 = b0 + wm + mt * 16 + g;
        #pragma unroll
        for (int nt = 0; nt < 4; nt++) {
            int col = n0 + wn + nt * 8 + t2;
            float2 e0, e1;
            e0.x = __expf(INV_EPS * acc[mt][nt][0]);
            e0.y = __expf(INV_EPS * acc[mt][nt][1]);
            e1.x = __expf(INV_EPS * acc[mt][nt][2]);
            e1.y = __expf(INV_EPS * acc[mt][nt][3]);
            *reinterpret_cast<__half2*>(&g_Eh[(size_t)r0 * KPAD + col]) =
                __floats2half2_rn(e0.x, e0.y);
            *reinterpret_cast<__half2*>(&g_Eh[(size_t)(r0 + 8) * KPAD + col]) =
                __floats2half2_rn(e1.x, e1.y);
            csum[nt][0] += e0.x + e1.x;
            csum[nt][1] += e0.y + e1.y;
        }
    }
    #pragma unroll
    for (int nt = 0; nt < 4; nt++) {
        atomicAdd(&scol[wn + nt * 8 + t2],     csum[nt][0]);
        atomicAdd(&scol[wn + nt * 8 + t2 + 1], csum[nt][1]);
    }
    __syncthreads();

    if (tid < 128) atomicAdd(&g_u[n0 + tid], scol[tid]);  // pads land in g_u[1000..1023]
    if (tid < 32) {
        float s = 0.f;
        #pragma unroll
        for (int i = 0; i < 4; i++) {
            int k = tid + i * 32;
            if (n0 + k < KCLS) s += scol[k];
        }
        s = warp_sum(s);
        if (tid == 0) atomicAdd(&g_S, (double)s);
    }

    // ---- Last block computes r1, zeroes u ----
    __threadfence();
    __syncthreads();
    if (tid == 0) sLast = (atomicAdd(&g_cnt, 1) == GEMM_GRID - 1);
    __syncthreads();
    if (sLast) finalize_r(tid);
}

// ---------------------------------------------------------------------------
// 3. Fused pass: warp-per-row over fp16 E (R12 structure, half the bytes,
//    ~100 regs -> 2 CTAs/SM). 384 blocks x 8 warps x 4 rows = 12288.
//    Per row: v = e.r (fp32 math); cb = SfB/v; uacc += e*cb (registers).
// ---------------------------------------------------------------------------
#define VCU_GRID 384
#define VCU_ROWS 4
__global__ __launch_bounds__(256) void k_vcu() {
    __shared__ float ush[KPAD];
    __shared__ int sLast;
    int tid = threadIdx.x, warp = tid >> 5, lane = tid & 31;
    for (int k = tid; k < KPAD; k += 256) ush[k] = 0.f;
    __syncthreads();

    float SfB = g_SfB;
    const float4* r4 = reinterpret_cast<const float4*>(g_r);
    int base = (blockIdx.x * 8 + warp) * VCU_ROWS;

    float uacc[32];
    #pragma unroll
    for (int i = 0; i < 32; i++) uacc[i] = 0.f;

    uint4 e[4], en[4];
    {
        const uint4* E16 = reinterpret_cast<const uint4*>(g_Eh + (size_t)base * KPAD);
        #pragma unroll
        for (int i = 0; i < 4; i++) e[i] = E16[lane + i * 32];
    }

    #pragma unroll
    for (int it = 0; it < VCU_ROWS; it++) {
        // Prefetch next row BEFORE the reduce (keeps the load stream busy)
        if (it + 1 < VCU_ROWS) {
            const uint4* En16 =
                reinterpret_cast<const uint4*>(g_Eh + (size_t)(base + it + 1) * KPAD);
            #pragma unroll
            for (int i = 0; i < 4; i++) en[i] = En16[lane + i * 32];
        }
        float ef[4][8];
        float v = 0.f;
        #pragma unroll
        for (int i = 0; i < 4; i++) {
            int j = lane + i * 32;               // uint4 index: halfs [8j, 8j+8)
            float2 f0 = __half22float2(*reinterpret_cast<__half2*>(&e[i].x));
            float2 f1 = __half22float2(*reinterpret_cast<__half2*>(&e[i].y));
            float2 f2 = __half22float2(*reinterpret_cast<__half2*>(&e[i].z));
            float2 f3 = __half22float2(*reinterpret_cast<__half2*>(&e[i].w));
            ef[i][0]=f0.x; ef[i][1]=f0.y; ef[i][2]=f1.x; ef[i][3]=f1.y;
            ef[i][4]=f2.x; ef[i][5]=f2.y; ef[i][6]=f3.x; ef[i][7]=f3.y;
            float4 ra = __ldg(&r4[2 * j]);
            float4 rb = __ldg(&r4[2 * j + 1]);
            v += ef[i][0]*ra.x + ef[i][1]*ra.y + ef[i][2]*ra.z + ef[i][3]*ra.w
               + ef[i][4]*rb.x + ef[i][5]*rb.y + ef[i][6]*rb.z + ef[i][7]*rb.w;
        }
        v = warp_sum(v);
        v = __shfl_sync(0xFFFFFFFFu, v, 0);
        float cb = SfB / v;                      // fp32 divide (no DP in loop)
        #pragma unroll
        for (int i = 0; i < 4; i++)
            #pragma unroll
            for (int q = 0; q < 8; q++) uacc[i * 8 + q] += ef[i][q] * cb;
        if (it + 1 < VCU_ROWS) {
            #pragma unroll
            for (int i = 0; i < 4; i++) e[i] = en[i];
        }
    }

    // Per-warp flush into block smem (spread addresses, one pass)
    #pragma unroll
    for (int i = 0; i < 4; i++) {
        int k0 = 8 * (lane + i * 32);
        #pragma unroll
        for (int q = 0; q < 8; q++) atomicAdd(&ush[k0 + q], uacc[i * 8 + q]);
    }
    __syncthreads();
    for (int k = tid; k < KPAD; k += 256) atomicAdd(&g_u[k], ush[k]);

    // ---- Last block computes next r, zeroes u ----
    __threadfence();
    __syncthreads();
    if (tid == 0) sLast = (atomicAdd(&g_cnt, 1) == VCU_GRID - 1);
    __syncthreads();
    if (sLast) finalize_r(tid);
}

// ---------------------------------------------------------------------------
// 4. Final fused pass (rows 0..4095) over fp16 E:
//    v_b = E[b,:].r3 ; out[b,:] = E * r3 / v_b (fp32 out).
//    128 blocks x 8 warps x 4 rows.
// ---------------------------------------------------------------------------
#define FIN_GRID 128
#define FIN_ROWS 4
__global__ __launch_bounds__(256) void k_final(float* __restrict__ out) {
    int warp = threadIdx.x >> 5, lane = threadIdx.x & 31;
    const float4* r4 = reinterpret_cast<const float4*>(g_r);
    int base = (blockIdx.x * 8 + warp) * FIN_ROWS;

    uint4 e[4], en[4];
    {
        const uint4* E16 = reinterpret_cast<const uint4*>(g_Eh + (size_t)base * KPAD);
        #pragma unroll
        for (int i = 0; i < 4; i++) e[i] = E16[lane + i * 32];
    }

    #pragma unroll
    for (int it = 0; it < FIN_ROWS; it++) {
        int b = base + it;
        if (it + 1 < FIN_ROWS) {
            const uint4* En16 =
                reinterpret_cast<const uint4*>(g_Eh + (size_t)(b + 1) * KPAD);
            #pragma unroll
            for (int i = 0; i < 4; i++) en[i] = En16[lane + i * 32];
        }
        float ef[4][8];
        float rr[4][8];
        float v = 0.f;
        #pragma unroll
        for (int i = 0; i < 4; i++) {
            int j = lane + i * 32;
            float2 f0 = __half22float2(*reinterpret_cast<__half2*>(&e[i].x));
            float2 f1 = __half22float2(*reinterpret_cast<__half2*>(&e[i].y));
            float2 f2 = __half22float2(*reinterpret_cast<__half2*>(&e[i].z));
            float2 f3 = __half22float2(*reinterpret_cast<__half2*>(&e[i].w));
            ef[i][0]=f0.x; ef[i][1]=f0.y; ef[i][2]=f1.x; ef[i][3]=f1.y;
            ef[i][4]=f2.x; ef[i][5]=f2.y; ef[i][6]=f3.x; ef[i][7]=f3.y;
            float4 ra = __ldg(&r4[2 * j]);
            float4 rb = __ldg(&r4[2 * j + 1]);
            rr[i][0]=ra.x; rr[i][1]=ra.y; rr[i][2]=ra.z; rr[i][3]=ra.w;
            rr[i][4]=rb.x; rr[i][5]=rb.y; rr[i][6]=rb.z; rr[i][7]=rb.w;
            #pragma unroll
            for (int q = 0; q < 8; q++) v += ef[i][q] * rr[i][q];
        }
        v = warp_sum(v);
        v = __shfl_sync(0xFFFFFFFFu, v, 0);
        float invv = 1.0f / v;
        float* orow = out + (size_t)b * KCLS;     // 4000*b bytes: 16B aligned
        #pragma unroll
        for (int i = 0; i < 4; i++) {
            int j = lane + i * 32;                // halfs [8j, 8j+8); valid j < 125
            if (j < KCLS / 8) {
                float4 o0, o1;
                o0.x = ef[i][0] * rr[i][0] * invv;
                o0.y = ef[i][1] * rr[i][1] * invv;
                o0.z = ef[i][2] * rr[i][2] * invv;
                o0.w = ef[i][3] * rr[i][3] * invv;
                o1.x = ef[i][4] * rr[i][4] * invv;
                o1.y = ef[i][5] * rr[i][5] * invv;
                o1.z = ef[i][6] * rr[i][6] * invv;
                o1.w = ef[i][7] * rr[i][7] * invv;
                *reinterpret_cast<float4*>(orow + 8 * j)     = o0;
                *reinterpret_cast<float4*>(orow + 8 * j + 4) = o1;
            }
        }
        if (it + 1 < FIN_ROWS) {
            #pragma unroll
            for (int i = 0; i < 4; i++) e[i] = en[i];
        }
    }
}

// ---------------------------------------------------------------------------
extern "C" void kernel_launch(void* const* d_in, const int* in_sizes, int n_in,
                              void* d_out, int out_size) {
    const float* features = (const float*)d_in[0];
    const float* head     = (const float*)d_in[1];
    const float* queue    = (const float*)d_in[2];
    float* out = (float*)d_out;

    cudaFuncSetAttribute(k_gemm_mma, cudaFuncAttributeMaxDynamicSharedMemorySize,
                         SMEM_GEMM_TOTAL);

    k_prep<<<PREP_GRID, 256>>>(features, queue, head);
    k_gemm_mma<<<dim3(KPAD / 128, B_TOT / 128), 256, SMEM_GEMM_TOTAL>>>();  // + r1
    k_vcu<<<VCU_GRID, 256>>>();   // iter1 col-step + iter2 row-sum -> r2
    k_vcu<<<VCU_GRID, 256>>>();   // iter2 col-step + iter3 row-sum -> r3
    k_final<<<FIN_GRID, 256>>>(out);  // iter3 col-step fused with output
}

// round 16
// speedup vs baseline: 1.1330x; 1.1330x over previous
#include <cuda_runtime.h>
#include <cuda_fp16.h>
#include <cstdint>

// Problem constants
#define B_TOT 12288   // features(4096) + queue(8192)
#define N_OUT 4096
#define KCLS  1000
#define KPAD  1024
#define DDIM  256
#define INV_EPS 20.0f

// ---------------------------------------------------------------------------
// Device scratch (allocation-free)
// ---------------------------------------------------------------------------
__device__ __half  g_Eh[B_TOT * KPAD];  // exp(logits/eps) in fp16, [b,1024] (25 MB)
__device__ __half  g_Ah[B_TOT * DDIM];  // normalized features, fp16
__device__ __half  g_Bh[KPAD * DDIM];   // normalized head^T, fp16 (pad rows stay 0)
__device__ float   g_u[KPAD];
__device__ float   g_r[KPAD];
__device__ float   g_c[B_TOT];
__device__ double  g_S;
__device__ float   g_SfB;               // (float)(S / B_TOT), set by finalize_r
__device__ int     g_cnt;               // last-block ticket (self-resetting)

__device__ __forceinline__ float warp_sum(float v) {
    #pragma unroll
    for (int o = 16; o > 0; o >>= 1) v += __shfl_down_sync(0xFFFFFFFFu, v, o);
    return v;
}

__device__ __forceinline__ uint32_t smem_u32(const void* p) {
    uint32_t a;
    asm("{ .reg .u64 t; cvta.to.shared.u64 t, %1; cvt.u32.u64 %0, t; }" : "=r"(a) : "l"(p));
    return a;
}

#define SW64(o) ((o) ^ (((o) >> 3) & 0x30))

__device__ __forceinline__ void ldsm_x4(uint32_t& r0, uint32_t& r1, uint32_t& r2, uint32_t& r3,
                                        uint32_t addr) {
    asm volatile("ldmatrix.sync.aligned.m8n8.x4.shared.b16 {%0,%1,%2,%3}, [%4];"
                 : "=r"(r0), "=r"(r1), "=r"(r2), "=r"(r3) : "r"(addr));
}

__device__ __forceinline__ void mma_f16(float* d, const uint32_t* a, const uint32_t* b) {
    asm volatile(
        "mma.sync.aligned.m16n8k16.row.col.f32.f16.f16.f32 "
        "{%0,%1,%2,%3}, {%4,%5,%6,%7}, {%8,%9}, {%0,%1,%2,%3};"
        : "+f"(d[0]), "+f"(d[1]), "+f"(d[2]), "+f"(d[3])
        : "r"(a[0]), "r"(a[1]), "r"(a[2]), "r"(a[3]), "r"(b[0]), "r"(b[1]));
}

__device__ __forceinline__ void cp_async16(uint32_t dst, const void* src) {
    asm volatile("cp.async.cg.shared.global [%0], [%1], 16;" :: "r"(dst), "l"(src));
}
__device__ __forceinline__ void cp_commit() {
    asm volatile("cp.async.commit_group;" ::: "memory");
}
template <int N> __device__ __forceinline__ void cp_wait() {
    asm volatile("cp.async.wait_group %0;" :: "n"(N) : "memory");
}

// Shared helper: compute r from (S, u), zero u, reset ticket, publish S/B as
// float. Call from the LAST block of a kernel (all threads of that block).
__device__ __forceinline__ void finalize_r(int tid) {
    double S = g_S;
    for (int k = tid; k < KPAD; k += 256) {
        float u;
        asm volatile("ld.global.cg.f32 %0, [%1];" : "=f"(u) : "l"(&g_u[k]));
        g_r[k] = (k < KCLS) ? (float)(S / ((double)KCLS * (double)u)) : 0.f;
        g_u[k] = 0.f;
    }
    if (tid == 0) {
        g_SfB = (float)(S / (double)B_TOT);
        g_cnt = 0;
    }
}

// ---------------------------------------------------------------------------
// 1. Merged prep: blocks [0,1536) normalize feature rows -> fp16 (warp/row);
//    blocks [1536,1792) normalize head dim d -> transposed fp16.
// ---------------------------------------------------------------------------
#define FEAT_BLOCKS (B_TOT / 8)          // 1536
#define PREP_GRID (FEAT_BLOCKS + DDIM)   // 1792

__global__ __launch_bounds__(256) void k_prep(const float* __restrict__ features,
                                              const float* __restrict__ queue,
                                              const float* __restrict__ head) {
    if (blockIdx.x == 0 && threadIdx.x == 0) g_S = 0.0;

    if (blockIdx.x < FEAT_BLOCKS) {
        int gwarp = (blockIdx.x * 256 + threadIdx.x) >> 5;
        int lane  = threadIdx.x & 31;
        const float* row = (gwarp < N_OUT) ? (features + (size_t)gwarp * DDIM)
                                           : (queue + (size_t)(gwarp - N_OUT) * DDIM);
        float x[8];
        const float4* r4 = reinterpret_cast<const float4*>(row + lane * 8);
        float4 v0 = r4[0], v1 = r4[1];
        x[0]=v0.x; x[1]=v0.y; x[2]=v0.z; x[3]=v0.w;
        x[4]=v1.x; x[5]=v1.y; x[6]=v1.z; x[7]=v1.w;
        float ss = 0.f;
        #pragma unroll
        for (int i = 0; i < 8; i++) ss += x[i] * x[i];
        ss = warp_sum(ss);
        ss = __shfl_sync(0xFFFFFFFFu, ss, 0);
        float inv = 1.0f / fmaxf(sqrtf(ss), 1e-12f);
        __half h[8];
        #pragma unroll
        for (int i = 0; i < 8; i++) h[i] = __float2half(x[i] * inv);
        *reinterpret_cast<uint4*>(&g_Ah[(size_t)gwarp * DDIM + lane * 8]) =
            *reinterpret_cast<uint4*>(h);
    } else {
        int d = blockIdx.x - FEAT_BLOCKS;
        const float* row = head + (size_t)d * KCLS;
        float ss = 0.f;
        for (int k = threadIdx.x; k < KCLS; k += 256) {
            float v = row[k];
            ss += v * v;
        }
        __shared__ float sred[8];
        ss = warp_sum(ss);
        if ((threadIdx.x & 31) == 0) sred[threadIdx.x >> 5] = ss;
        __syncthreads();
        if (threadIdx.x < 8) {
            float s = sred[threadIdx.x];
            #pragma unroll
            for (int o = 4; o > 0; o >>= 1) s += __shfl_down_sync(0xFFu, s, o);
            if (threadIdx.x == 0) sred[0] = 1.0f / fmaxf(sqrtf(s), 1e-12f);
        }
        __syncthreads();
        float inv = sred[0];
        for (int k = threadIdx.x; k < KCLS; k += 256)
            g_Bh[(size_t)k * DDIM + d] = __float2half(row[k] * inv);
    }
}

// ---------------------------------------------------------------------------
// 2. HMMA GEMM + exp, single fp16 pass, 3-stage cp.async pipeline.
//    E stored as fp16. Last block computes r1 from (S, u0), zeroes u.
// ---------------------------------------------------------------------------
#define CH 32
#define NCH 8
#define TILE_BYTES 8192                   // 128 rows x 64B
#define STAGE_BYTES (2 * TILE_BYTES)      // A, B
#define NSTAGE 3
#define SMEM_GEMM_TOTAL (NSTAGE * STAGE_BYTES + 512)
#define GEMM_GRID (8 * 96)

__device__ __forceinline__ void load_stage(uint32_t sbase, int buf, int b0, int n0,
                                           int c, int tid) {
    uint32_t dstb = sbase + (uint32_t)buf * STAGE_BYTES;
    #pragma unroll
    for (int j = 0; j < 2; j++) {
        int slot = tid + j * 256;          // 0..511
        int row  = slot >> 2;
        int c16  = slot & 3;
        uint32_t sw = SW64((uint32_t)(row * 64 + c16 * 16));
        size_t gA = (size_t)(b0 + row) * DDIM + c * CH + c16 * 8;
        size_t gB = (size_t)(n0 + row) * DDIM + c * CH + c16 * 8;
        cp_async16(dstb + 0 * TILE_BYTES + sw, &g_Ah[gA]);
        cp_async16(dstb + 1 * TILE_BYTES + sw, &g_Bh[gB]);
    }
}

__global__ __launch_bounds__(256, 2) void k_gemm_mma() {
    extern __shared__ char smem[];
    float* scol = reinterpret_cast<float*>(smem + NSTAGE * STAGE_BYTES);
    __shared__ int sLast;
    uint32_t sbase = smem_u32(smem);

    int tid = threadIdx.x, wid = tid >> 5, lane = tid & 31;
    int n0 = blockIdx.x * 128;
    int b0 = blockIdx.y * 128;
    int wm = (wid & 1) * 64;
    int wn = (wid >> 1) * 32;

    float acc[4][4][4];
    #pragma unroll
    for (int i = 0; i < 4; i++)
        #pragma unroll
        for (int j = 0; j < 4; j++)
            #pragma unroll
            for (int q = 0; q < 4; q++) acc[i][j][q] = 0.f;

    int a_row  = (lane & 7) + ((lane >> 3) & 1) * 8;
    int a_colb = (lane >> 4) * 16;
    int b_row  = (lane & 7) + ((lane >> 4) & 1) * 8;
    int b_colb = ((lane >> 3) & 1) * 16;

    #pragma unroll
    for (int s = 0; s < NSTAGE; s++) { load_stage(sbase, s, b0, n0, s, tid); cp_commit(); }

    for (int c = 0; c < NCH; c++) {
        cp_wait<NSTAGE - 1>();
        __syncthreads();
        uint32_t tb = sbase + (uint32_t)(c % NSTAGE) * STAGE_BYTES;

        #pragma unroll
        for (int ks = 0; ks < 2; ks++) {
            uint32_t a[4][4], bh[4][2];
            #pragma unroll
            for (int np = 0; np < 2; np++) {
                uint32_t sw = SW64((uint32_t)((wn + np * 16 + b_row) * 64 + ks * 32 + b_colb));
                ldsm_x4(bh[np*2][0], bh[np*2][1], bh[np*2+1][0], bh[np*2+1][1],
                        tb + 1 * TILE_BYTES + sw);
            }
            #pragma unroll
            for (int mt = 0; mt < 4; mt++) {
                uint32_t sw = SW64((uint32_t)((wm + mt * 16 + a_row) * 64 + ks * 32 + a_colb));
                ldsm_x4(a[mt][0], a[mt][1], a[mt][2], a[mt][3], tb + 0 * TILE_BYTES + sw);
            }
            #pragma unroll
            for (int mt = 0; mt < 4; mt++)
                #pragma unroll
                for (int nt = 0; nt < 4; nt++)
                    mma_f16(acc[mt][nt], a[mt], bh[nt]);
        }
        __syncthreads();
        if (c + NSTAGE < NCH) load_stage(sbase, c % NSTAGE, b0, n0, c + NSTAGE, tid);
        cp_commit();
    }

    // ---- Epilogue: exp, fp16 stores, column sums ----
    if (tid < 128) scol[tid] = 0.f;
    __syncthreads();

    int g = lane >> 2;
    int t2 = (lane & 3) * 2;
    float csum[4][2];
    #pragma unroll
    for (int nt = 0; nt < 4; nt++) { csum[nt][0] = 0.f; csum[nt][1] = 0.f; }

    #pragma unroll
    for (int mt = 0; mt < 4; mt++) {
        int r0 = b0 + wm + mt * 16 + g;
        #pragma unroll
        for (int nt = 0; nt < 4; nt++) {
            int col = n0 + wn + nt * 8 + t2;
            float2 e0, e1;
            e0.x = __expf(INV_EPS * acc[mt][nt][0]);
            e0.y = __expf(INV_EPS * acc[mt][nt][1]);
            e1.x = __expf(INV_EPS * acc[mt][nt][2]);
            e1.y = __expf(INV_EPS * acc[mt][nt][3]);
            *reinterpret_cast<__half2*>(&g_Eh[(size_t)r0 * KPAD + col]) =
                __floats2half2_rn(e0.x, e0.y);
            *reinterpret_cast<__half2*>(&g_Eh[(size_t)(r0 + 8) * KPAD + col]) =
                __floats2half2_rn(e1.x, e1.y);
            csum[nt][0] += e0.x + e1.x;
            csum[nt][1] += e0.y + e1.y;
        }
    }
    #pragma unroll
    for (int nt = 0; nt < 4; nt++) {
        atomicAdd(&scol[wn + nt * 8 + t2],     csum[nt][0]);
        atomicAdd(&scol[wn + nt * 8 + t2 + 1], csum[nt][1]);
    }
    __syncthreads();

    if (tid < 128) atomicAdd(&g_u[n0 + tid], scol[tid]);  // pads land in g_u[1000..1023]
    if (tid < 32) {
        float s = 0.f;
        #pragma unroll
        for (int i = 0; i < 4; i++) {
            int k = tid + i * 32;
            if (n0 + k < KCLS) s += scol[k];
        }
        s = warp_sum(s);
        if (tid == 0) atomicAdd(&g_S, (double)s);
    }

    // ---- Last block computes r1, zeroes u ----
    __threadfence();
    __syncthreads();
    if (tid == 0) sLast = (atomicAdd(&g_cnt, 1) == GEMM_GRID - 1);
    __syncthreads();
    if (sLast) finalize_r(tid);
}

// ---------------------------------------------------------------------------
// 3. Row pass (v + c only, NO u accumulation -> low regs, high occupancy):
//    warp-per-2-rows; batch both rows' 4 uint4 loads up front (MLP = 8).
//    768 blocks x 8 warps x 2 rows = 12288. Writes g_c[b] = SfB / v_b.
// ---------------------------------------------------------------------------
#define KV_GRID 768
__global__ __launch_bounds__(256) void k_v() {
    int tid = threadIdx.x, warp = tid >> 5, lane = tid & 31;
    float SfB = g_SfB;
    const float4* r4 = reinterpret_cast<const float4*>(g_r);
    int base = (blockIdx.x * 8 + warp) * 2;

    const uint4* E0 = reinterpret_cast<const uint4*>(g_Eh + (size_t)base * KPAD);
    const uint4* E1 = reinterpret_cast<const uint4*>(g_Eh + (size_t)(base + 1) * KPAD);
    uint4 e0[4], e1[4];
    #pragma unroll
    for (int i = 0; i < 4; i++) e0[i] = E0[lane + i * 32];
    #pragma unroll
    for (int i = 0; i < 4; i++) e1[i] = E1[lane + i * 32];

    float v0 = 0.f, v1 = 0.f;
    #pragma unroll
    for (int i = 0; i < 4; i++) {
        int j = lane + i * 32;
        float4 ra = __ldg(&r4[2 * j]);
        float4 rb = __ldg(&r4[2 * j + 1]);
        float2 a0 = __half22float2(*reinterpret_cast<__half2*>(&e0[i].x));
        float2 a1 = __half22float2(*reinterpret_cast<__half2*>(&e0[i].y));
        float2 a2 = __half22float2(*reinterpret_cast<__half2*>(&e0[i].z));
        float2 a3 = __half22float2(*reinterpret_cast<__half2*>(&e0[i].w));
        v0 += a0.x*ra.x + a0.y*ra.y + a1.x*ra.z + a1.y*ra.w
            + a2.x*rb.x + a2.y*rb.y + a3.x*rb.z + a3.y*rb.w;
        float2 b0 = __half22float2(*reinterpret_cast<__half2*>(&e1[i].x));
        float2 b1 = __half22float2(*reinterpret_cast<__half2*>(&e1[i].y));
        float2 b2 = __half22float2(*reinterpret_cast<__half2*>(&e1[i].z));
        float2 b3 = __half22float2(*reinterpret_cast<__half2*>(&e1[i].w));
        v1 += b0.x*ra.x + b0.y*ra.y + b1.x*ra.z + b1.y*ra.w
            + b2.x*rb.x + b2.y*rb.y + b3.x*rb.z + b3.y*rb.w;
    }
    v0 = warp_sum(v0);
    v1 = warp_sum(v1);
    if (lane == 0) {
        g_c[base]     = SfB / v0;
        g_c[base + 1] = SfB / v1;
    }
}

// ---------------------------------------------------------------------------
// 4. Column pass (u only): thread owns uint4 col-group j = tid&127;
//    grid-strides rows with fully INDEPENDENT loads (no barriers/shuffles).
//    128 blocks x 96 rows. Ends with ticket -> finalize_r (next r).
// ---------------------------------------------------------------------------
#define KU_GRID 128
#define KU_ROWS 96
__global__ __launch_bounds__(256) void k_u() {
    __shared__ float ush[KPAD];
    __shared__ int sLast;
    int tid = threadIdx.x;
    for (int k = tid; k < KPAD; k += 256) ush[k] = 0.f;
    __syncthreads();

    int j   = tid & 127;          // column group (8 halfs)
    int sub = tid >> 7;           // 0/1: even/odd rows
    const uint4* E16 = reinterpret_cast<const uint4*>(g_Eh);
    float acc[8];
    #pragma unroll
    for (int q = 0; q < 8; q++) acc[q] = 0.f;

    int row0 = blockIdx.x * KU_ROWS + sub;
    #pragma unroll 4
    for (int i = 0; i < KU_ROWS / 2; i++) {
        int b = row0 + 2 * i;
        uint4 e = E16[(size_t)b * 128 + j];
        float cb = __ldg(&g_c[b]);
        float2 f0 = __half22float2(*reinterpret_cast<__half2*>(&e.x));
        float2 f1 = __half22float2(*reinterpret_cast<__half2*>(&e.y));
        float2 f2 = __half22float2(*reinterpret_cast<__half2*>(&e.z));
        float2 f3 = __half22float2(*reinterpret_cast<__half2*>(&e.w));
        acc[0] += f0.x * cb; acc[1] += f0.y * cb;
        acc[2] += f1.x * cb; acc[3] += f1.y * cb;
        acc[4] += f2.x * cb; acc[5] += f2.y * cb;
        acc[6] += f3.x * cb; acc[7] += f3.y * cb;
    }
    // Two threads share each j: combine via smem atomics (2-way only)
    #pragma unroll
    for (int q = 0; q < 8; q++) atomicAdd(&ush[j * 8 + q], acc[q]);
    __syncthreads();
    for (int k = tid; k < KPAD; k += 256) atomicAdd(&g_u[k], ush[k]);

    // ---- Last block computes next r, zeroes u ----
    __threadfence();
    __syncthreads();
    if (tid == 0) sLast = (atomicAdd(&g_cnt, 1) == KU_GRID - 1);
    __syncthreads();
    if (sLast) finalize_r(tid);
}

// ---------------------------------------------------------------------------
// 5. Final fused pass (rows 0..4095) over fp16 E:
//    v_b = E[b,:].r3 ; out[b,:] = E * r3 / v_b (fp32 out).
//    128 blocks x 8 warps x 4 rows.
// ---------------------------------------------------------------------------
#define FIN_GRID 128
#define FIN_ROWS 4
__global__ __launch_bounds__(256) void k_final(float* __restrict__ out) {
    int warp = threadIdx.x >> 5, lane = threadIdx.x & 31;
    const float4* r4 = reinterpret_cast<const float4*>(g_r);
    int base = (blockIdx.x * 8 + warp) * FIN_ROWS;

    uint4 e[4], en[4];
    {
        const uint4* E16 = reinterpret_cast<const uint4*>(g_Eh + (size_t)base * KPAD);
        #pragma unroll
        for (int i = 0; i < 4; i++) e[i] = E16[lane + i * 32];
    }

    #pragma unroll
    for (int it = 0; it < FIN_ROWS; it++) {
        int b = base + it;
        if (it + 1 < FIN_ROWS) {
            const uint4* En16 =
                reinterpret_cast<const uint4*>(g_Eh + (size_t)(b + 1) * KPAD);
            #pragma unroll
            for (int i = 0; i < 4; i++) en[i] = En16[lane + i * 32];
        }
        float ef[4][8];
        float rr[4][8];
        float v = 0.f;
        #pragma unroll
        for (int i = 0; i < 4; i++) {
            int j = lane + i * 32;
            float2 f0 = __half22float2(*reinterpret_cast<__half2*>(&e[i].x));
            float2 f1 = __half22float2(*reinterpret_cast<__half2*>(&e[i].y));
            float2 f2 = __half22float2(*reinterpret_cast<__half2*>(&e[i].z));
            float2 f3 = __half22float2(*reinterpret_cast<__half2*>(&e[i].w));
            ef[i][0]=f0.x; ef[i][1]=f0.y; ef[i][2]=f1.x; ef[i][3]=f1.y;
            ef[i][4]=f2.x; ef[i][5]=f2.y; ef[i][6]=f3.x; ef[i][7]=f3.y;
            float4 ra = __ldg(&r4[2 * j]);
            float4 rb = __ldg(&r4[2 * j + 1]);
            rr[i][0]=ra.x; rr[i][1]=ra.y; rr[i][2]=ra.z; rr[i][3]=ra.w;
            rr[i][4]=rb.x; rr[i][5]=rb.y; rr[i][6]=rb.z; rr[i][7]=rb.w;
            #pragma unroll
            for (int q = 0; q < 8; q++) v += ef[i][q] * rr[i][q];
        }
        v = warp_sum(v);
        v = __shfl_sync(0xFFFFFFFFu, v, 0);
        float invv = 1.0f / v;
        float* orow = out + (size_t)b * KCLS;     // 4000*b bytes: 16B aligned
        #pragma unroll
        for (int i = 0; i < 4; i++) {
            int j = lane + i * 32;                // halfs [8j, 8j+8); valid j < 125
            if (j < KCLS / 8) {
                float4 o0, o1;
                o0.x = ef[i][0] * rr[i][0] * invv;
                o0.y = ef[i][1] * rr[i][1] * invv;
                o0.z = ef[i][2] * rr[i][2] * invv;
                o0.w = ef[i][3] * rr[i][3] * invv;
                o1.x = ef[i][4] * rr[i][4] * invv;
                o1.y = ef[i][5] * rr[i][5] * invv;
                o1.z = ef[i][6] * rr[i][6] * invv;
                o1.w = ef[i][7] * rr[i][7] * invv;
                *reinterpret_cast<float4*>(orow + 8 * j)     = o0;
                *reinterpret_cast<float4*>(orow + 8 * j + 4) = o1;
            }
        }
        if (it + 1 < FIN_ROWS) {
            #pragma unroll
            for (int i = 0; i < 4; i++) e[i] = en[i];
        }
    }
}

// ---------------------------------------------------------------------------
extern "C" void kernel_launch(void* const* d_in, const int* in_sizes, int n_in,
                              void* d_out, int out_size) {
    const float* features = (const float*)d_in[0];
    const float* head     = (const float*)d_in[1];
    const float* queue    = (const float*)d_in[2];
    float* out = (float*)d_out;

    cudaFuncSetAttribute(k_gemm_mma, cudaFuncAttributeMaxDynamicSharedMemorySize,
                         SMEM_GEMM_TOTAL);

    k_prep<<<PREP_GRID, 256>>>(features, queue, head);
    k_gemm_mma<<<dim3(KPAD / 128, B_TOT / 128), 256, SMEM_GEMM_TOTAL>>>();  // + r1
    // iter 1: row pass (c1), column pass (u1 -> r2)
    k_v<<<KV_GRID, 256>>>();
    k_u<<<KU_GRID, 256>>>();
    // iter 2: row pass (c2), column pass (u2 -> r3)
    k_v<<<KV_GRID, 256>>>();
    k_u<<<KU_GRID, 256>>>();
    // iter 3 col-step fused with output (rows < 4096)
    k_final<<<FIN_GRID, 256>>>(out);
}